// round 15
// baseline (speedup 1.0000x reference)
#include <cuda_runtime.h>

// ---------------------------------------------------------------------------
// ShiftSpecificCrossAttention — tf32 mma.
// attn: 512-thread CTAs (16 warps, R14-validated).
// out:  ROWB=16, 256-thread CTAs, 3 CTAs/SM (24 warps/SM) — R14 profile
//       showed out_kernel still warp-starved at occ 25% / issue 18.8%.
// ---------------------------------------------------------------------------

#define D_MODEL   512
#define N_SHIFTS  8
#define N_HEADS   8
#define B_SZ      2048
#define K_NBR     64
#define SH        64
#define SCALE     0.125f
#define LN_EPS    1e-5f

#define EP   516
#define QP   132
#define PP   68
#define ROWB 16

typedef unsigned int u32;

__device__ __forceinline__ float tf32r(float x) {
    float y; asm("cvt.rna.tf32.f32 %0, %1;" : "=f"(y) : "f"(x)); return y;
}
__device__ __forceinline__ float4 tf32r4(float4 v) {
    v.x = tf32r(v.x); v.y = tf32r(v.y); v.z = tf32r(v.z); v.w = tf32r(v.w);
    return v;
}
__device__ __forceinline__ void mma8(float* c, const u32* a, const u32* b) {
    asm volatile(
        "mma.sync.aligned.m16n8k8.row.col.f32.tf32.tf32.f32 "
        "{%0,%1,%2,%3},{%4,%5,%6,%7},{%8,%9},{%0,%1,%2,%3};"
        : "+f"(c[0]), "+f"(c[1]), "+f"(c[2]), "+f"(c[3])
        : "r"(a[0]), "r"(a[1]), "r"(a[2]), "r"(a[3]), "r"(b[0]), "r"(b[1]));
}

__device__ __align__(16) float g_Q[N_SHIFTS * D_MODEL];
__device__ __align__(16) float g_QW[SH * D_MODEL];
__device__ float g_qb[SH];
__device__ float g_anyvalid[B_SZ];
__device__ __align__(16) float g_ctx[(size_t)B_SZ * SH * D_MODEL];

// ---------------------------------------------------------------------------
__global__ void qproj_kernel(const float* __restrict__ shift,
                             const float* __restrict__ Wq,
                             const float* __restrict__ bq) {
    int gidx = blockIdx.x * blockDim.x + threadIdx.x;
    if (gidx >= N_SHIFTS * D_MODEL) return;
    int s = gidx / D_MODEL, i = gidx % D_MODEL;
    const float* sr = shift + s * D_MODEL;
    const float* wr = Wq + (size_t)i * D_MODEL;
    float a0 = 0.f, a1 = 0.f, a2 = 0.f, a3 = 0.f;
    #pragma unroll 4
    for (int d = 0; d < D_MODEL; d += 4) {
        a0 += sr[d + 0] * wr[d + 0];
        a1 += sr[d + 1] * wr[d + 1];
        a2 += sr[d + 2] * wr[d + 2];
        a3 += sr[d + 3] * wr[d + 3];
    }
    g_Q[gidx] = bq[i] + ((a0 + a1) + (a2 + a3));
}

// ---------------------------------------------------------------------------
__global__ void qw_kernel(const float* __restrict__ Wk,
                          const float* __restrict__ bk) {
    __shared__ float Qs[64];
    int r = blockIdx.x;
    int h = r / N_SHIFTS, s = r % N_SHIFTS;
    int t = threadIdx.x;
    if (t < 64) Qs[t] = g_Q[s * D_MODEL + h * 64 + t];
    __syncthreads();
    #pragma unroll
    for (int jj = 0; jj < 4; jj++) {
        int c = t + jj * 128;
        float acc = 0.f;
        #pragma unroll 8
        for (int hd = 0; hd < 64; hd++)
            acc += Qs[hd] * Wk[(size_t)(h * 64 + hd) * D_MODEL + c];
        g_QW[r * D_MODEL + c] = tf32r(acc * SCALE);
    }
    if (t == 0) {
        float acc = 0.f;
        for (int hd = 0; hd < 64; hd++)
            acc += Qs[hd] * bk[h * 64 + hd];
        g_qb[r] = acc * SCALE;
    }
}

// ---------------------------------------------------------------------------
// B: per-batch attention, 512 threads (16 warps). smem ~184KB, 1 CTA/SM.
// (unchanged from R14 — measured good)
// ---------------------------------------------------------------------------
__global__ __launch_bounds__(512, 1)
void attn_kernel(const float* __restrict__ enc,
                 const int* __restrict__ valid,
                 const float* __restrict__ dist,
                 const float* __restrict__ cs_ptr) {
    extern __shared__ float sm[];
    float* enc_s  = sm;                       // 64*516
    float* qwch   = enc_s + 64 * EP;          // 64*132
    float* P_s    = qwch + 64 * QP;           // 64*68
    float* bias_s = P_s + 64 * PP;            // 64
    float* keep_s = bias_s + 64;              // 64
    float* qb_s   = keep_s + 64;              // 64
    float* any_s  = qb_s + 64;                // 4

    const int b = blockIdx.x, t = threadIdx.x;
    const int w = t >> 5, l = t & 31, g = l >> 2, tg = l & 3;
    const float cs = cs_ptr[0];

    const float4* encg = (const float4*)(enc + (size_t)b * K_NBR * D_MODEL);
    #pragma unroll 1
    for (int i = t; i < 64 * 128; i += 512) {
        int k = i >> 7, c4 = i & 127;
        *(float4*)&enc_s[k * EP + c4 * 4] = tf32r4(encg[i]);
    }
    if (t < 64) {
        bias_s[t] = dist[b * K_NBR + t] * cs;
        keep_s[t] = (valid[b * K_NBR + t] != 0) ? 1.f : 0.f;
        qb_s[t] = g_qb[t];
    }
    if (t == 0) any_s[0] = 0.f;
    __syncthreads();
    if (t < 64 && keep_s[t] != 0.f) any_s[0] = 1.f;   // benign same-value race

    // logits: 16 warps = 4m x 4n
    const int mi = w >> 2, nj0 = (w & 3) * 2;
    float accL[2][4];
    #pragma unroll
    for (int j = 0; j < 2; j++)
        #pragma unroll
        for (int e = 0; e < 4; e++) accL[j][e] = 0.f;

    #pragma unroll 1
    for (int ch = 0; ch < 4; ch++) {
        #pragma unroll 1
        for (int i = t; i < 64 * 32; i += 512) {
            int r = i >> 5, c = i & 31;
            *(float4*)&qwch[r * QP + c * 4] =
                *(const float4*)&g_QW[r * D_MODEL + ch * 128 + c * 4];
        }
        __syncthreads();
        #pragma unroll 2
        for (int ks = 0; ks < 16; ks++) {
            int kb = ks * 8;
            u32 a[4];
            a[0] = __float_as_uint(qwch[(mi * 16 + g) * QP + kb + tg]);
            a[1] = __float_as_uint(qwch[(mi * 16 + g + 8) * QP + kb + tg]);
            a[2] = __float_as_uint(qwch[(mi * 16 + g) * QP + kb + tg + 4]);
            a[3] = __float_as_uint(qwch[(mi * 16 + g + 8) * QP + kb + tg + 4]);
            #pragma unroll
            for (int j = 0; j < 2; j++) {
                const float* Bb = enc_s + ((nj0 + j) * 8 + g) * EP + ch * 128 + kb;
                u32 bb_[2] = {__float_as_uint(Bb[tg]), __float_as_uint(Bb[tg + 4])};
                mma8(accL[j], a, bb_);
            }
        }
        __syncthreads();
    }
    {
        int r0 = mi * 16 + g, r1 = r0 + 8;
        float q0 = qb_s[r0], q1 = qb_s[r1];
        #pragma unroll
        for (int j = 0; j < 2; j++) {
            int c0 = (nj0 + j) * 8 + 2 * tg, c1 = c0 + 1;
            float bi0 = bias_s[c0], bi1 = bias_s[c1];
            bool k0 = keep_s[c0] != 0.f, k1 = keep_s[c1] != 0.f;
            P_s[r0 * PP + c0] = k0 ? accL[j][0] + q0 + bi0 : -10000.0f;
            P_s[r0 * PP + c1] = k1 ? accL[j][1] + q0 + bi1 : -10000.0f;
            P_s[r1 * PP + c0] = k0 ? accL[j][2] + q1 + bi0 : -10000.0f;
            P_s[r1 * PP + c1] = k1 ? accL[j][3] + q1 + bi1 : -10000.0f;
        }
    }
    __syncthreads();

    // softmax (4 rows per warp)
    #pragma unroll 1
    for (int rr = 0; rr < 4; rr++) {
        int hs = w * 4 + rr;
        float v0 = P_s[hs * PP + l], v1 = P_s[hs * PP + l + 32];
        float m = fmaxf(v0, v1);
        #pragma unroll
        for (int o = 16; o > 0; o >>= 1) m = fmaxf(m, __shfl_xor_sync(~0u, m, o));
        float e0 = __expf(v0 - m), e1 = __expf(v1 - m);
        float ssum = e0 + e1;
        #pragma unroll
        for (int o = 16; o > 0; o >>= 1) ssum += __shfl_xor_sync(~0u, ssum, o);
        float inv = 1.f / ssum;
        P_s[hs * PP + l] = tf32r(e0 * inv);
        P_s[hs * PP + l + 32] = tf32r(e1 * inv);
    }
    __syncthreads();

    // ctx = P @ enc : 16 warps = 2m x 8n-groups
    const int mg = w >> 3, ng = w & 7;
    float* cg = g_ctx + (size_t)b * SH * D_MODEL;
    {
        float acc[2][8][4];
        #pragma unroll
        for (int mt = 0; mt < 2; mt++)
            #pragma unroll
            for (int nt = 0; nt < 8; nt++)
                #pragma unroll
                for (int e = 0; e < 4; e++) acc[mt][nt][e] = 0.f;
        #pragma unroll 2
        for (int ks = 0; ks < 8; ks++) {
            int kb = ks * 8;
            u32 a[2][4];
            #pragma unroll
            for (int mt = 0; mt < 2; mt++) {
                int rb = (mg * 2 + mt) * 16;
                a[mt][0] = __float_as_uint(P_s[(rb + g) * PP + kb + tg]);
                a[mt][1] = __float_as_uint(P_s[(rb + g + 8) * PP + kb + tg]);
                a[mt][2] = __float_as_uint(P_s[(rb + g) * PP + kb + tg + 4]);
                a[mt][3] = __float_as_uint(P_s[(rb + g + 8) * PP + kb + tg + 4]);
            }
            #pragma unroll
            for (int nt = 0; nt < 8; nt++) {
                int ncol = (ng * 8 + nt) * 8 + g;
                u32 bb_[2] = {__float_as_uint(enc_s[(kb + tg) * EP + ncol]),
                              __float_as_uint(enc_s[(kb + tg + 4) * EP + ncol])};
                mma8(acc[0][nt], a[0], bb_);
                mma8(acc[1][nt], a[1], bb_);
            }
        }
        #pragma unroll
        for (int mt = 0; mt < 2; mt++) {
            int r0 = (mg * 2 + mt) * 16 + g;
            #pragma unroll
            for (int nt = 0; nt < 8; nt++) {
                int c0 = (ng * 8 + nt) * 8 + 2 * tg;
                *(float2*)&cg[(size_t)r0 * D_MODEL + c0] =
                    make_float2(acc[mt][nt][0], acc[mt][nt][1]);
                *(float2*)&cg[(size_t)(r0 + 8) * D_MODEL + c0] =
                    make_float2(acc[mt][nt][2], acc[mt][nt][3]);
            }
        }
    }
    if (t == 0) g_anyvalid[b] = any_s[0];
}

// ---------------------------------------------------------------------------
// C: 16 rows per CTA, 256 threads (8 warps), 3 CTAs/SM. smem ~74KB.
// stage1: tmp2 = per-head ctx @ Wv_h^T + bv ; stage2: out = tmp2 @ Wo^T ; LN.
// ---------------------------------------------------------------------------
__global__ __launch_bounds__(256, 3)
void out_kernel(const float* __restrict__ Wv, const float* __restrict__ bv,
                const float* __restrict__ Wo, const float* __restrict__ bo,
                const float* __restrict__ shift,
                const float* __restrict__ lnw, const float* __restrict__ lnb,
                float* __restrict__ out) {
    extern __shared__ float sm[];
    float* tmp2  = sm;                    // 16*516 = 8256
    float* buf   = tmp2 + 16 * EP;        // 8448 (stage1: 16*68 a + 64*68 wv; stage2: 64*132 wo)
    float* bo_s  = buf + 8448;            // 512
    float* bv_s  = bo_s + 512;            // 512
    float* lnw_s = bv_s + 512;            // 512
    float* lnb_s = lnw_s + 512;           // 512
    float* rsum  = lnb_s + 512;           // 16*8 = 128
    float* rsq   = rsum + 128;            // 128

    const int t = threadIdx.x;
    const int w = t >> 5, l = t & 31, g = l >> 2, tg = l & 3;
    const int rowbase = blockIdx.x * ROWB;

    #pragma unroll 1
    for (int i = t; i < 512; i += 256) {
        bo_s[i] = bo[i]; bv_s[i] = bv[i]; lnw_s[i] = lnw[i]; lnb_s[i] = lnb[i];
    }

    // ================= stage 1: tmp2 = ctx @ Wv_h^T + bv =================
    // one head per iteration; 8 warps; warp tile m16 x n8 (warp w -> n-tile w)
    float* abuf  = buf;                   // 16 x 68
    float* wvbuf = buf + 16 * PP;         // 64 x 68

    #pragma unroll 1
    for (int h = 0; h < 8; h++) {
        float acc[4] = {0.f, 0.f, 0.f, 0.f};
        #pragma unroll 1
        for (int kc = 0; kc < 8; kc++) {
            __syncthreads();   // previous chunk's reads (and tmp2 writes) done
            {   // stage ctx: 16 rows x 64 K = 256 float4, one per thread
                int r = t >> 4, c4 = t & 15;
                int gr = rowbase + r, bb = gr >> 3, ss = gr & 7;
                float4 v = *(const float4*)
                    &g_ctx[((size_t)bb * SH + h * 8 + ss) * D_MODEL + kc * 64 + c4 * 4];
                *(float4*)&abuf[r * PP + c4 * 4] = tf32r4(v);
            }
            #pragma unroll 1
            for (int i = t; i < 1024; i += 256) {   // Wv: 64 rows x 64 K
                int r = i >> 4, c4 = i & 15;
                float4 v = *(const float4*)
                    &Wv[((size_t)h * 64 + r) * D_MODEL + kc * 64 + c4 * 4];
                *(float4*)&wvbuf[r * PP + c4 * 4] = tf32r4(v);
            }
            __syncthreads();
            #pragma unroll 2
            for (int ks = 0; ks < 8; ks++) {
                int kb = ks * 8;
                u32 a[4];
                a[0] = __float_as_uint(abuf[g * PP + kb + tg]);
                a[1] = __float_as_uint(abuf[(g + 8) * PP + kb + tg]);
                a[2] = __float_as_uint(abuf[g * PP + kb + tg + 4]);
                a[3] = __float_as_uint(abuf[(g + 8) * PP + kb + tg + 4]);
                int nrow = w * 8 + g;
                u32 bb_[2] = {__float_as_uint(wvbuf[nrow * PP + kb + tg]),
                              __float_as_uint(wvbuf[nrow * PP + kb + tg + 4])};
                mma8(acc, a, bb_);
            }
        }
        // write head's tmp2 block (+bv, tf32-rounded); next barrier orders it
        {
            int c0 = h * 64 + w * 8 + 2 * tg;
            tmp2[g * EP + c0]           = tf32r(acc[0] + bv_s[c0]);
            tmp2[g * EP + c0 + 1]       = tf32r(acc[1] + bv_s[c0 + 1]);
            tmp2[(g + 8) * EP + c0]     = tf32r(acc[2] + bv_s[c0]);
            tmp2[(g + 8) * EP + c0 + 1] = tf32r(acc[3] + bv_s[c0 + 1]);
        }
    }

    // ================= stage 2: out = tmp2 @ Wo^T (acc in regs) ==========
    // nb loop over 8 blocks of 64 cols; warp w -> n-tile w within block.
    float acc2[8][4];
    #pragma unroll
    for (int nb = 0; nb < 8; nb++)
        #pragma unroll
        for (int e = 0; e < 4; e++) acc2[nb][e] = 0.f;

    #pragma unroll
    for (int nb = 0; nb < 8; nb++) {
        #pragma unroll 1
        for (int kc = 0; kc < 4; kc++) {   // K chunks of 128
            __syncthreads();               // orders tmp2 writes / prior reads
            #pragma unroll 1
            for (int i = t; i < 2048; i += 256) {   // Wo: 64 rows x 128 K
                int r = i >> 5, c4 = i & 31;
                float4 v = *(const float4*)
                    &Wo[((size_t)(nb * 64 + r)) * D_MODEL + kc * 128 + c4 * 4];
                *(float4*)&buf[r * QP + c4 * 4] = tf32r4(v);
            }
            __syncthreads();
            #pragma unroll 2
            for (int ks = 0; ks < 16; ks++) {
                int kb = ks * 8;
                const float* Ab = tmp2 + kc * 128 + kb;
                u32 a[4];
                a[0] = __float_as_uint(Ab[g * EP + tg]);
                a[1] = __float_as_uint(Ab[(g + 8) * EP + tg]);
                a[2] = __float_as_uint(Ab[g * EP + tg + 4]);
                a[3] = __float_as_uint(Ab[(g + 8) * EP + tg + 4]);
                int nrow = w * 8 + g;
                u32 bb_[2] = {__float_as_uint(buf[nrow * QP + kb + tg]),
                              __float_as_uint(buf[nrow * QP + kb + tg + 4])};
                mma8(acc2[nb], a, bb_);
            }
        }
    }

    // ================= LayerNorm + residual + mask =======================
    // thread rows: g and g+8 (both have s = g); cols: nb*64 + w*8 + 2tg(+1)
    const float* shrow = shift + g * D_MODEL;   // s = g for both rows
    float psum[2] = {0.f, 0.f};
    float psq[2]  = {0.f, 0.f};
    #pragma unroll
    for (int nb = 0; nb < 8; nb++) {
        int c0 = nb * 64 + w * 8 + 2 * tg;
        float add0 = bo_s[c0] + __ldg(&shrow[c0]);
        float add1 = bo_s[c0 + 1] + __ldg(&shrow[c0 + 1]);
        float x0 = acc2[nb][0] + add0;
        float x1 = acc2[nb][1] + add1;
        float x2 = acc2[nb][2] + add0;
        float x3 = acc2[nb][3] + add1;
        acc2[nb][0] = x0; acc2[nb][1] = x1;
        acc2[nb][2] = x2; acc2[nb][3] = x3;
        psum[0] += x0 + x1; psq[0] += x0 * x0 + x1 * x1;
        psum[1] += x2 + x3; psq[1] += x2 * x2 + x3 * x3;
    }
    #pragma unroll
    for (int hf = 0; hf < 2; hf++) {
        #pragma unroll
        for (int o = 1; o <= 2; o <<= 1) {
            psum[hf] += __shfl_xor_sync(~0u, psum[hf], o);
            psq[hf]  += __shfl_xor_sync(~0u, psq[hf], o);
        }
    }
    if (tg == 0) {
        rsum[g * 8 + w] = psum[0];        rsq[g * 8 + w] = psq[0];
        rsum[(g + 8) * 8 + w] = psum[1];  rsq[(g + 8) * 8 + w] = psq[1];
    }
    __syncthreads();

    float mu[2], rstd[2], av[2];
    #pragma unroll
    for (int hf = 0; hf < 2; hf++) {
        int row = g + hf * 8;
        float s = 0.f, sq = 0.f;
        #pragma unroll
        for (int ww2 = 0; ww2 < 8; ww2++) {
            s  += rsum[row * 8 + ww2];
            sq += rsq[row * 8 + ww2];
        }
        float m = s * (1.f / D_MODEL);
        mu[hf] = m;
        rstd[hf] = rsqrtf(sq * (1.f / D_MODEL) - m * m + LN_EPS);
        av[hf] = g_anyvalid[(rowbase + row) >> 3];
    }

    #pragma unroll
    for (int nb = 0; nb < 8; nb++) {
        int c0 = nb * 64 + w * 8 + 2 * tg;
        float w0 = lnw_s[c0], w1 = lnw_s[c0 + 1];
        float b0v = lnb_s[c0], b1v = lnb_s[c0 + 1];
        float y0 = ((acc2[nb][0] - mu[0]) * rstd[0] * w0 + b0v) * av[0];
        float y1 = ((acc2[nb][1] - mu[0]) * rstd[0] * w1 + b1v) * av[0];
        float y2 = ((acc2[nb][2] - mu[1]) * rstd[1] * w0 + b0v) * av[1];
        float y3 = ((acc2[nb][3] - mu[1]) * rstd[1] * w1 + b1v) * av[1];
        *(float2*)&out[(size_t)(rowbase + g) * D_MODEL + c0] = make_float2(y0, y1);
        *(float2*)&out[(size_t)(rowbase + g + 8) * D_MODEL + c0] = make_float2(y2, y3);
    }
}

// ---------------------------------------------------------------------------
extern "C" void kernel_launch(void* const* d_in, const int* in_sizes, int n_in,
                              void* d_out, int out_size) {
    (void)in_sizes; (void)n_in; (void)out_size;
    const float* enc   = (const float*)d_in[0];
    const int*   valid = (const int*)d_in[1];
    const float* dist  = (const float*)d_in[2];
    const float* shift = (const float*)d_in[3];
    const float* Wq    = (const float*)d_in[4];
    const float* bq    = (const float*)d_in[5];
    const float* Wk    = (const float*)d_in[6];
    const float* bk    = (const float*)d_in[7];
    const float* Wv    = (const float*)d_in[8];
    const float* bv    = (const float*)d_in[9];
    const float* Wo    = (const float*)d_in[10];
    const float* bo    = (const float*)d_in[11];
    const float* lnw   = (const float*)d_in[12];
    const float* lnb   = (const float*)d_in[13];
    const float* cs    = (const float*)d_in[14];

    const int smemB = (64 * EP + 64 * QP + 64 * PP + 4 * 64) * 4;
    const int smemC = (16 * EP + 8448 + 4 * 512 + 2 * 128) * 4;
    cudaFuncSetAttribute(attn_kernel, cudaFuncAttributeMaxDynamicSharedMemorySize, smemB);
    cudaFuncSetAttribute(out_kernel,  cudaFuncAttributeMaxDynamicSharedMemorySize, smemC);

    qproj_kernel<<<(N_SHIFTS * D_MODEL + 127) / 128, 128>>>(shift, Wq, bq);
    qw_kernel<<<SH, 128>>>(Wk, bk);
    attn_kernel<<<B_SZ, 512, smemB>>>(enc, valid, dist, cs);
    out_kernel<<<(B_SZ * N_SHIFTS) / ROWB, 256, smemC>>>(Wv, bv, Wo, bo, shift,
                                                         lnw, lnb, (float*)d_out);
}

// round 16
// speedup vs baseline: 1.4207x; 1.4207x over previous
#include <cuda_runtime.h>

// ---------------------------------------------------------------------------
// ShiftSpecificCrossAttention — tf32 mma.
// attn: 512-thread CTAs (R14-validated), writes tf32-pre-rounded ctx.
// out:  R14 shape (ROWB=64, 512 thr, 1 CTA/SM; measured 516us) with all
//       cvt.rna.tf32 removed from staging loops (weights pre-rounded by
//       wprep_kernel into g_Wv/g_Wo; ctx pre-rounded by attn).
// R15 lesson: ROWB=16 regressed (staging amortization lost > warp gain).
// ---------------------------------------------------------------------------

#define D_MODEL   512
#define N_SHIFTS  8
#define N_HEADS   8
#define B_SZ      2048
#define K_NBR     64
#define SH        64
#define SCALE     0.125f
#define LN_EPS    1e-5f

#define EP   516
#define QP   132
#define PP   68
#define ROWB 64

typedef unsigned int u32;

__device__ __forceinline__ float tf32r(float x) {
    float y; asm("cvt.rna.tf32.f32 %0, %1;" : "=f"(y) : "f"(x)); return y;
}
__device__ __forceinline__ float4 tf32r4(float4 v) {
    v.x = tf32r(v.x); v.y = tf32r(v.y); v.z = tf32r(v.z); v.w = tf32r(v.w);
    return v;
}
__device__ __forceinline__ void mma8(float* c, const u32* a, const u32* b) {
    asm volatile(
        "mma.sync.aligned.m16n8k8.row.col.f32.tf32.tf32.f32 "
        "{%0,%1,%2,%3},{%4,%5,%6,%7},{%8,%9},{%0,%1,%2,%3};"
        : "+f"(c[0]), "+f"(c[1]), "+f"(c[2]), "+f"(c[3])
        : "r"(a[0]), "r"(a[1]), "r"(a[2]), "r"(a[3]), "r"(b[0]), "r"(b[1]));
}

__device__ __align__(16) float g_Q[N_SHIFTS * D_MODEL];
__device__ __align__(16) float g_QW[SH * D_MODEL];
__device__ float g_qb[SH];
__device__ float g_anyvalid[B_SZ];
__device__ __align__(16) float g_ctx[(size_t)B_SZ * SH * D_MODEL];   // tf32-rounded
__device__ __align__(16) float g_Wv[D_MODEL * D_MODEL];              // tf32-rounded
__device__ __align__(16) float g_Wo[D_MODEL * D_MODEL];              // tf32-rounded

// ---------------------------------------------------------------------------
// prep: pre-round Wv/Wo to tf32 once (removes cvt from out_kernel hot loops)
// ---------------------------------------------------------------------------
__global__ void wprep_kernel(const float* __restrict__ Wv,
                             const float* __restrict__ Wo) {
    int i = blockIdx.x * blockDim.x + threadIdx.x;
    if (i < D_MODEL * D_MODEL / 4) {
        *(float4*)&g_Wv[i * 4] = tf32r4(*(const float4*)&Wv[i * 4]);
        *(float4*)&g_Wo[i * 4] = tf32r4(*(const float4*)&Wo[i * 4]);
    }
}

// ---------------------------------------------------------------------------
__global__ void qproj_kernel(const float* __restrict__ shift,
                             const float* __restrict__ Wq,
                             const float* __restrict__ bq) {
    int gidx = blockIdx.x * blockDim.x + threadIdx.x;
    if (gidx >= N_SHIFTS * D_MODEL) return;
    int s = gidx / D_MODEL, i = gidx % D_MODEL;
    const float* sr = shift + s * D_MODEL;
    const float* wr = Wq + (size_t)i * D_MODEL;
    float a0 = 0.f, a1 = 0.f, a2 = 0.f, a3 = 0.f;
    #pragma unroll 4
    for (int d = 0; d < D_MODEL; d += 4) {
        a0 += sr[d + 0] * wr[d + 0];
        a1 += sr[d + 1] * wr[d + 1];
        a2 += sr[d + 2] * wr[d + 2];
        a3 += sr[d + 3] * wr[d + 3];
    }
    g_Q[gidx] = bq[i] + ((a0 + a1) + (a2 + a3));
}

// ---------------------------------------------------------------------------
__global__ void qw_kernel(const float* __restrict__ Wk,
                          const float* __restrict__ bk) {
    __shared__ float Qs[64];
    int r = blockIdx.x;
    int h = r / N_SHIFTS, s = r % N_SHIFTS;
    int t = threadIdx.x;
    if (t < 64) Qs[t] = g_Q[s * D_MODEL + h * 64 + t];
    __syncthreads();
    #pragma unroll
    for (int jj = 0; jj < 4; jj++) {
        int c = t + jj * 128;
        float acc = 0.f;
        #pragma unroll 8
        for (int hd = 0; hd < 64; hd++)
            acc += Qs[hd] * Wk[(size_t)(h * 64 + hd) * D_MODEL + c];
        g_QW[r * D_MODEL + c] = tf32r(acc * SCALE);
    }
    if (t == 0) {
        float acc = 0.f;
        for (int hd = 0; hd < 64; hd++)
            acc += Qs[hd] * bk[h * 64 + hd];
        g_qb[r] = acc * SCALE;
    }
}

// ---------------------------------------------------------------------------
// B: per-batch attention, 512 threads (16 warps). smem ~184KB, 1 CTA/SM.
// ---------------------------------------------------------------------------
__global__ __launch_bounds__(512, 1)
void attn_kernel(const float* __restrict__ enc,
                 const int* __restrict__ valid,
                 const float* __restrict__ dist,
                 const float* __restrict__ cs_ptr) {
    extern __shared__ float sm[];
    float* enc_s  = sm;                       // 64*516
    float* qwch   = enc_s + 64 * EP;          // 64*132
    float* P_s    = qwch + 64 * QP;           // 64*68
    float* bias_s = P_s + 64 * PP;            // 64
    float* keep_s = bias_s + 64;              // 64
    float* qb_s   = keep_s + 64;              // 64
    float* any_s  = qb_s + 64;                // 4

    const int b = blockIdx.x, t = threadIdx.x;
    const int w = t >> 5, l = t & 31, g = l >> 2, tg = l & 3;
    const float cs = cs_ptr[0];

    const float4* encg = (const float4*)(enc + (size_t)b * K_NBR * D_MODEL);
    #pragma unroll 1
    for (int i = t; i < 64 * 128; i += 512) {
        int k = i >> 7, c4 = i & 127;
        *(float4*)&enc_s[k * EP + c4 * 4] = tf32r4(encg[i]);
    }
    if (t < 64) {
        bias_s[t] = dist[b * K_NBR + t] * cs;
        keep_s[t] = (valid[b * K_NBR + t] != 0) ? 1.f : 0.f;
        qb_s[t] = g_qb[t];
    }
    if (t == 0) any_s[0] = 0.f;
    __syncthreads();
    if (t < 64 && keep_s[t] != 0.f) any_s[0] = 1.f;   // benign same-value race

    // logits: 16 warps = 4m x 4n
    const int mi = w >> 2, nj0 = (w & 3) * 2;
    float accL[2][4];
    #pragma unroll
    for (int j = 0; j < 2; j++)
        #pragma unroll
        for (int e = 0; e < 4; e++) accL[j][e] = 0.f;

    #pragma unroll 1
    for (int ch = 0; ch < 4; ch++) {
        #pragma unroll 1
        for (int i = t; i < 64 * 32; i += 512) {
            int r = i >> 5, c = i & 31;
            *(float4*)&qwch[r * QP + c * 4] =
                *(const float4*)&g_QW[r * D_MODEL + ch * 128 + c * 4];
        }
        __syncthreads();
        #pragma unroll 2
        for (int ks = 0; ks < 16; ks++) {
            int kb = ks * 8;
            u32 a[4];
            a[0] = __float_as_uint(qwch[(mi * 16 + g) * QP + kb + tg]);
            a[1] = __float_as_uint(qwch[(mi * 16 + g + 8) * QP + kb + tg]);
            a[2] = __float_as_uint(qwch[(mi * 16 + g) * QP + kb + tg + 4]);
            a[3] = __float_as_uint(qwch[(mi * 16 + g + 8) * QP + kb + tg + 4]);
            #pragma unroll
            for (int j = 0; j < 2; j++) {
                const float* Bb = enc_s + ((nj0 + j) * 8 + g) * EP + ch * 128 + kb;
                u32 bb_[2] = {__float_as_uint(Bb[tg]), __float_as_uint(Bb[tg + 4])};
                mma8(accL[j], a, bb_);
            }
        }
        __syncthreads();
    }
    {
        int r0 = mi * 16 + g, r1 = r0 + 8;
        float q0 = qb_s[r0], q1 = qb_s[r1];
        #pragma unroll
        for (int j = 0; j < 2; j++) {
            int c0 = (nj0 + j) * 8 + 2 * tg, c1 = c0 + 1;
            float bi0 = bias_s[c0], bi1 = bias_s[c1];
            bool k0 = keep_s[c0] != 0.f, k1 = keep_s[c1] != 0.f;
            P_s[r0 * PP + c0] = k0 ? accL[j][0] + q0 + bi0 : -10000.0f;
            P_s[r0 * PP + c1] = k1 ? accL[j][1] + q0 + bi1 : -10000.0f;
            P_s[r1 * PP + c0] = k0 ? accL[j][2] + q1 + bi0 : -10000.0f;
            P_s[r1 * PP + c1] = k1 ? accL[j][3] + q1 + bi1 : -10000.0f;
        }
    }
    __syncthreads();

    // softmax (4 rows per warp)
    #pragma unroll 1
    for (int rr = 0; rr < 4; rr++) {
        int hs = w * 4 + rr;
        float v0 = P_s[hs * PP + l], v1 = P_s[hs * PP + l + 32];
        float m = fmaxf(v0, v1);
        #pragma unroll
        for (int o = 16; o > 0; o >>= 1) m = fmaxf(m, __shfl_xor_sync(~0u, m, o));
        float e0 = __expf(v0 - m), e1 = __expf(v1 - m);
        float ssum = e0 + e1;
        #pragma unroll
        for (int o = 16; o > 0; o >>= 1) ssum += __shfl_xor_sync(~0u, ssum, o);
        float inv = 1.f / ssum;
        P_s[hs * PP + l] = tf32r(e0 * inv);
        P_s[hs * PP + l + 32] = tf32r(e1 * inv);
    }
    __syncthreads();

    // ctx = P @ enc : 16 warps = 2m x 8n-groups; store tf32-rounded
    const int mg = w >> 3, ng = w & 7;
    float* cg = g_ctx + (size_t)b * SH * D_MODEL;
    {
        float acc[2][8][4];
        #pragma unroll
        for (int mt = 0; mt < 2; mt++)
            #pragma unroll
            for (int nt = 0; nt < 8; nt++)
                #pragma unroll
                for (int e = 0; e < 4; e++) acc[mt][nt][e] = 0.f;
        #pragma unroll 2
        for (int ks = 0; ks < 8; ks++) {
            int kb = ks * 8;
            u32 a[2][4];
            #pragma unroll
            for (int mt = 0; mt < 2; mt++) {
                int rb = (mg * 2 + mt) * 16;
                a[mt][0] = __float_as_uint(P_s[(rb + g) * PP + kb + tg]);
                a[mt][1] = __float_as_uint(P_s[(rb + g + 8) * PP + kb + tg]);
                a[mt][2] = __float_as_uint(P_s[(rb + g) * PP + kb + tg + 4]);
                a[mt][3] = __float_as_uint(P_s[(rb + g + 8) * PP + kb + tg + 4]);
            }
            #pragma unroll
            for (int nt = 0; nt < 8; nt++) {
                int ncol = (ng * 8 + nt) * 8 + g;
                u32 bb_[2] = {__float_as_uint(enc_s[(kb + tg) * EP + ncol]),
                              __float_as_uint(enc_s[(kb + tg + 4) * EP + ncol])};
                mma8(acc[0][nt], a[0], bb_);
                mma8(acc[1][nt], a[1], bb_);
            }
        }
        #pragma unroll
        for (int mt = 0; mt < 2; mt++) {
            int r0 = (mg * 2 + mt) * 16 + g;
            #pragma unroll
            for (int nt = 0; nt < 8; nt++) {
                int c0 = (ng * 8 + nt) * 8 + 2 * tg;
                *(float2*)&cg[(size_t)r0 * D_MODEL + c0] =
                    make_float2(tf32r(acc[mt][nt][0]), tf32r(acc[mt][nt][1]));
                *(float2*)&cg[(size_t)(r0 + 8) * D_MODEL + c0] =
                    make_float2(tf32r(acc[mt][nt][2]), tf32r(acc[mt][nt][3]));
            }
        }
    }
    if (t == 0) g_anyvalid[b] = any_s[0];
}

// ---------------------------------------------------------------------------
// C: 64 rows per CTA, 512 threads (16 warps). smem ~223KB, 1 CTA/SM.
// Staging loops are pure copies (inputs pre-rounded).
// ---------------------------------------------------------------------------
__global__ __launch_bounds__(512, 1)
void out_kernel(const float* __restrict__ bv,
                const float* __restrict__ bo,
                const float* __restrict__ shift,
                const float* __restrict__ lnw, const float* __restrict__ lnb,
                float* __restrict__ out) {
    extern __shared__ float sm[];
    float* tmp2    = sm;                      // 64*516
    float* buf     = tmp2 + 64 * EP;          // 17408
    float* bo_s    = buf + 17408;             // 512
    float* bv_s    = bo_s + 512;              // 512
    float* lnw_s   = bv_s + 512;              // 512
    float* lnb_s   = lnw_s + 512;             // 512
    float* shift_s = lnb_s + 512;             // 4096
    float* rsum    = shift_s + 4096;          // 256
    float* rsq     = rsum + 256;              // 256

    const int t = threadIdx.x;
    const int w = t >> 5, l = t & 31, g = l >> 2, tg = l & 3;
    const int rowbase = blockIdx.x * ROWB;

    #pragma unroll 1
    for (int i = t; i < 512; i += 512) {
        bo_s[i] = bo[i]; bv_s[i] = bv[i]; lnw_s[i] = lnw[i]; lnb_s[i] = lnb[i];
    }
    #pragma unroll 1
    for (int i = t; i < 4096; i += 512) shift_s[i] = shift[i];

    // ================= stage 1: tmp2 = ctx @ Wv_h^T + bv =================
    // 2 heads staged per iteration; 8 warps per head; warp tile 2m x 2n.
    const int hh  = w >> 3;
    const int ww  = w & 7;
    const int mgs = ww >> 2, ngg = ww & 3;
    float* abuf  = buf;              // [slot][64][68]
    float* wvbuf = buf + 2 * 64 * PP;

    #pragma unroll 1
    for (int it = 0; it < 4; it++) {
        float acc[2][2][4];
        #pragma unroll
        for (int mt = 0; mt < 2; mt++)
            #pragma unroll
            for (int nt = 0; nt < 2; nt++)
                #pragma unroll
                for (int e = 0; e < 4; e++) acc[mt][nt][e] = 0.f;

        #pragma unroll 1
        for (int kc = 0; kc < 8; kc++) {
            __syncthreads();   // previous chunk's reads complete
            #pragma unroll 1
            for (int i = t; i < 2048; i += 512) {
                int slot = i >> 10, rem = i & 1023, r = rem >> 4, c4 = rem & 15;
                int h = it * 2 + slot;
                int gr = rowbase + r, bb = gr >> 3, ss = gr & 7;
                *(float4*)&abuf[slot * 64 * PP + r * PP + c4 * 4] = *(const float4*)
                    &g_ctx[((size_t)bb * SH + h * 8 + ss) * D_MODEL + kc * 64 + c4 * 4];
            }
            #pragma unroll 1
            for (int i = t; i < 2048; i += 512) {
                int slot = i >> 10, rem = i & 1023, r = rem >> 4, c4 = rem & 15;
                int h = it * 2 + slot;
                *(float4*)&wvbuf[slot * 64 * PP + r * PP + c4 * 4] = *(const float4*)
                    &g_Wv[((size_t)h * 64 + r) * D_MODEL + kc * 64 + c4 * 4];
            }
            __syncthreads();
            const float* Ab = abuf + hh * 64 * PP;
            const float* Wb = wvbuf + hh * 64 * PP;
            #pragma unroll 2
            for (int ks = 0; ks < 8; ks++) {
                int kb = ks * 8;
                u32 a[2][4];
                #pragma unroll
                for (int mt = 0; mt < 2; mt++) {
                    int rb = (mgs * 2 + mt) * 16;
                    a[mt][0] = __float_as_uint(Ab[(rb + g) * PP + kb + tg]);
                    a[mt][1] = __float_as_uint(Ab[(rb + g + 8) * PP + kb + tg]);
                    a[mt][2] = __float_as_uint(Ab[(rb + g) * PP + kb + tg + 4]);
                    a[mt][3] = __float_as_uint(Ab[(rb + g + 8) * PP + kb + tg + 4]);
                }
                #pragma unroll
                for (int nt = 0; nt < 2; nt++) {
                    int nrow = (ngg * 2 + nt) * 8 + g;
                    u32 bb_[2] = {__float_as_uint(Wb[nrow * PP + kb + tg]),
                                  __float_as_uint(Wb[nrow * PP + kb + tg + 4])};
                    mma8(acc[0][nt], a[0], bb_);
                    mma8(acc[1][nt], a[1], bb_);
                }
            }
        }
        // write this head's tmp2 block (+bv, tf32-rounded)
        int h = it * 2 + hh;
        #pragma unroll
        for (int mt = 0; mt < 2; mt++) {
            int r0 = (mgs * 2 + mt) * 16 + g;
            #pragma unroll
            for (int nt = 0; nt < 2; nt++) {
                int c0 = h * 64 + (ngg * 2 + nt) * 8 + 2 * tg;
                tmp2[r0 * EP + c0]           = tf32r(acc[mt][nt][0] + bv_s[c0]);
                tmp2[r0 * EP + c0 + 1]       = tf32r(acc[mt][nt][1] + bv_s[c0 + 1]);
                tmp2[(r0 + 8) * EP + c0]     = tf32r(acc[mt][nt][2] + bv_s[c0]);
                tmp2[(r0 + 8) * EP + c0 + 1] = tf32r(acc[mt][nt][3] + bv_s[c0 + 1]);
            }
        }
    }

    // ================= stage 2: out = tmp2 @ Wo^T (acc in regs) ==========
    // 16 warps = 4m x 4n-quarters; warp = 16 rows x 128 cols (32 per nb).
    const int mg2 = w >> 2, ng2 = w & 3;
    float acc2[4][4][4];
    #pragma unroll
    for (int nb = 0; nb < 4; nb++)
        #pragma unroll
        for (int nt = 0; nt < 4; nt++)
            #pragma unroll
            for (int e = 0; e < 4; e++) acc2[nb][nt][e] = 0.f;

    #pragma unroll
    for (int nb = 0; nb < 4; nb++) {
        #pragma unroll 1
        for (int kc = 0; kc < 4; kc++) {
            __syncthreads();
            #pragma unroll 1
            for (int i = t; i < 4096; i += 512) {
                int r = i >> 5, c4 = i & 31;
                *(float4*)&buf[r * QP + c4 * 4] = *(const float4*)
                    &g_Wo[((size_t)(nb * 128 + r)) * D_MODEL + kc * 128 + c4 * 4];
            }
            __syncthreads();
            #pragma unroll 2
            for (int ks = 0; ks < 16; ks++) {
                int kb = ks * 8;
                u32 a[4];
                {
                    int rb = mg2 * 16;
                    const float* Ab = tmp2 + kc * 128 + kb;
                    a[0] = __float_as_uint(Ab[(rb + g) * EP + tg]);
                    a[1] = __float_as_uint(Ab[(rb + g + 8) * EP + tg]);
                    a[2] = __float_as_uint(Ab[(rb + g) * EP + tg + 4]);
                    a[3] = __float_as_uint(Ab[(rb + g + 8) * EP + tg + 4]);
                }
                #pragma unroll
                for (int nt = 0; nt < 4; nt++) {
                    int nrow = (ng2 * 4 + nt) * 8 + g;
                    u32 bb_[2] = {__float_as_uint(buf[nrow * QP + kb + tg]),
                                  __float_as_uint(buf[nrow * QP + kb + tg + 4])};
                    mma8(acc2[nb][nt], a, bb_);
                }
            }
        }
    }

    // ================= LayerNorm + residual + mask =======================
    const int ssg = g & 7;
    float psum[2] = {0.f, 0.f};
    float psq[2]  = {0.f, 0.f};
    #pragma unroll
    for (int nb = 0; nb < 4; nb++)
        #pragma unroll
        for (int nt = 0; nt < 4; nt++) {
            int c0 = nb * 128 + (ng2 * 4 + nt) * 8 + 2 * tg;
            float add0 = bo_s[c0] + shift_s[ssg * 512 + c0];
            float add1 = bo_s[c0 + 1] + shift_s[ssg * 512 + c0 + 1];
            float x0 = acc2[nb][nt][0] + add0;
            float x1 = acc2[nb][nt][1] + add1;
            float x2 = acc2[nb][nt][2] + add0;
            float x3 = acc2[nb][nt][3] + add1;
            acc2[nb][nt][0] = x0; acc2[nb][nt][1] = x1;
            acc2[nb][nt][2] = x2; acc2[nb][nt][3] = x3;
            psum[0] += x0 + x1; psq[0] += x0 * x0 + x1 * x1;
            psum[1] += x2 + x3; psq[1] += x2 * x2 + x3 * x3;
        }
    #pragma unroll
    for (int hf = 0; hf < 2; hf++) {
        #pragma unroll
        for (int o = 1; o <= 2; o <<= 1) {
            psum[hf] += __shfl_xor_sync(~0u, psum[hf], o);
            psq[hf]  += __shfl_xor_sync(~0u, psq[hf], o);
        }
    }
    if (tg == 0) {
        #pragma unroll
        for (int hf = 0; hf < 2; hf++) {
            int row = mg2 * 16 + g + hf * 8;
            rsum[row * 4 + ng2] = psum[hf];
            rsq[row * 4 + ng2]  = psq[hf];
        }
    }
    __syncthreads();

    float mu[2], rstd[2], av[2];
    #pragma unroll
    for (int hf = 0; hf < 2; hf++) {
        int row = mg2 * 16 + g + hf * 8;
        float s  = rsum[row * 4] + rsum[row * 4 + 1] + rsum[row * 4 + 2] + rsum[row * 4 + 3];
        float sq = rsq[row * 4] + rsq[row * 4 + 1] + rsq[row * 4 + 2] + rsq[row * 4 + 3];
        float m = s * (1.f / D_MODEL);
        mu[hf] = m;
        rstd[hf] = rsqrtf(sq * (1.f / D_MODEL) - m * m + LN_EPS);
        av[hf] = g_anyvalid[(rowbase + row) >> 3];
    }

    #pragma unroll
    for (int nb = 0; nb < 4; nb++)
        #pragma unroll
        for (int nt = 0; nt < 4; nt++) {
            int c0 = nb * 128 + (ng2 * 4 + nt) * 8 + 2 * tg;
            float w0 = lnw_s[c0], w1 = lnw_s[c0 + 1];
            float b0v = lnb_s[c0], b1v = lnb_s[c0 + 1];
            int r0 = mg2 * 16 + g;
            float y0 = ((acc2[nb][nt][0] - mu[0]) * rstd[0] * w0 + b0v) * av[0];
            float y1 = ((acc2[nb][nt][1] - mu[0]) * rstd[0] * w1 + b1v) * av[0];
            float y2 = ((acc2[nb][nt][2] - mu[1]) * rstd[1] * w0 + b0v) * av[1];
            float y3 = ((acc2[nb][nt][3] - mu[1]) * rstd[1] * w1 + b1v) * av[1];
            *(float2*)&out[(size_t)(rowbase + r0) * D_MODEL + c0] = make_float2(y0, y1);
            *(float2*)&out[(size_t)(rowbase + r0 + 8) * D_MODEL + c0] = make_float2(y2, y3);
        }
}

// ---------------------------------------------------------------------------
extern "C" void kernel_launch(void* const* d_in, const int* in_sizes, int n_in,
                              void* d_out, int out_size) {
    (void)in_sizes; (void)n_in; (void)out_size;
    const float* enc   = (const float*)d_in[0];
    const int*   valid = (const int*)d_in[1];
    const float* dist  = (const float*)d_in[2];
    const float* shift = (const float*)d_in[3];
    const float* Wq    = (const float*)d_in[4];
    const float* bq    = (const float*)d_in[5];
    const float* Wk    = (const float*)d_in[6];
    const float* bk    = (const float*)d_in[7];
    const float* Wv    = (const float*)d_in[8];
    const float* bv    = (const float*)d_in[9];
    const float* Wo    = (const float*)d_in[10];
    const float* bo    = (const float*)d_in[11];
    const float* lnw   = (const float*)d_in[12];
    const float* lnb   = (const float*)d_in[13];
    const float* cs    = (const float*)d_in[14];

    const int smemB = (64 * EP + 64 * QP + 64 * PP + 4 * 64) * 4;
    const int smemC = (64 * EP + 17408 + 4 * 512 + 4096 + 2 * 256) * 4;
    cudaFuncSetAttribute(attn_kernel, cudaFuncAttributeMaxDynamicSharedMemorySize, smemB);
    cudaFuncSetAttribute(out_kernel,  cudaFuncAttributeMaxDynamicSharedMemorySize, smemC);

    wprep_kernel<<<(D_MODEL * D_MODEL / 4 + 255) / 256, 256>>>(Wv, Wo);
    qproj_kernel<<<(N_SHIFTS * D_MODEL + 127) / 128, 128>>>(shift, Wq, bq);
    qw_kernel<<<SH, 128>>>(Wk, bk);
    attn_kernel<<<B_SZ, 512, smemB>>>(enc, valid, dist, cs);
    out_kernel<<<(B_SZ * N_SHIFTS) / ROWB, 512, smemC>>>(bv, bo, shift,
                                                         lnw, lnb, (float*)d_out);
}